// round 4
// baseline (speedup 1.0000x reference)
#include <cuda_runtime.h>
#include <cuda_bf16.h>

#define BATCH 32
#define NPTS  2048
#define MPTS  2048
#define ITERS 5
#define PAIR_THREADS 128
#define SPLIT (NPTS / PAIR_THREADS)   // 16 -> grid 16 x 32 = 512 CTAs
#define LOG2E 1.4426950408889634f

// Persistent per-batch state (device globals: no allocation allowed)
__device__ float g_T[BATCH][6];     // r00 r01 tx  r10 r11 ty
__device__ float g_acc[BATCH][8];   // Sst.x Sst.y Stc.x Stc.y C00 C01 C10 C11

// ---------------- packed f32x2 helpers (sm_100+ PTX) ----------------
typedef unsigned long long u64;

__device__ __forceinline__ u64 pk2(float lo, float hi) {
    u64 r; asm("mov.b64 %0, {%1,%2};" : "=l"(r) : "f"(lo), "f"(hi)); return r;
}
__device__ __forceinline__ void upk2(u64 v, float& lo, float& hi) {
    asm("mov.b64 {%0,%1}, %2;" : "=f"(lo), "=f"(hi) : "l"(v));
}
__device__ __forceinline__ u64 fma2(u64 a, u64 b, u64 c) {
    u64 d; asm("fma.rn.f32x2 %0, %1, %2, %3;" : "=l"(d) : "l"(a), "l"(b), "l"(c)); return d;
}
__device__ __forceinline__ u64 add2(u64 a, u64 b) {
    u64 d; asm("add.rn.f32x2 %0, %1, %2;" : "=l"(d) : "l"(a), "l"(b)); return d;
}
__device__ __forceinline__ float ex2(float x) {
    float r; asm("ex2.approx.f32 %0, %1;" : "=f"(r) : "f"(x)); return r;
}

// ---------------- init: T = vec2mat(init), zero accumulators ----------------
__global__ void icp_init(const float* __restrict__ init) {
    int b = threadIdx.x;
    if (b >= BATCH) return;
    float th = init[3 * b + 0];
    float tx = init[3 * b + 1];
    float ty = init[3 * b + 2];
    float s, c;
    sincosf(th, &s, &c);
    float* T = g_T[b];
    T[0] = c;  T[1] = -s; T[2] = tx;
    T[3] = s;  T[4] = c;  T[5] = ty;
#pragma unroll
    for (int k = 0; k < 8; k++) g_acc[b][k] = 0.0f;
}

// ---------------- pair kernel: one row per thread, stream all M targets ----------------
__global__ __launch_bounds__(PAIR_THREADS)
void icp_pair(const float* __restrict__ source, const float* __restrict__ target) {
    __shared__ __align__(16) float sA[MPTS];
    __shared__ __align__(16) float sB[MPTS];
    __shared__ __align__(16) float sD[MPTS];
    __shared__ __align__(16) float sX[MPTS];
    __shared__ __align__(16) float sY[MPTS];

    const int b   = blockIdx.y;
    const int tid = threadIdx.x;

    // fill per-target params (A = 2*log2e*tx, B = 2*log2e*ty, D = -log2e*|t|^2)
    const float2* t2 = reinterpret_cast<const float2*>(target) + b * MPTS;
    for (int j = tid; j < MPTS; j += PAIR_THREADS) {
        float2 t = t2[j];
        sX[j] = t.x;
        sY[j] = t.y;
        sA[j] = 2.0f * LOG2E * t.x;
        sB[j] = 2.0f * LOG2E * t.y;
        sD[j] = -LOG2E * (t.x * t.x + t.y * t.y);
    }

    // transform this thread's source row: st = R*s + t
    const float* T = g_T[b];
    float T00 = T[0], T01 = T[1], T02 = T[2];
    float T10 = T[3], T11 = T[4], T12 = T[5];
    const int row = blockIdx.x * PAIR_THREADS + tid;
    const float2 s2 = reinterpret_cast<const float2*>(source)[b * NPTS + row];
    float stx = T00 * s2.x + T01 * s2.y + T02;
    float sty = T10 * s2.x + T11 * s2.y + T12;
    float c0  = -LOG2E * (stx * stx + sty * sty);   // makes arg == -log2e * dist^2 exactly

    __syncthreads();

    u64 vsx = pk2(stx, stx);
    u64 vsy = pk2(sty, sty);
    u64 vc0 = pk2(c0, c0);
    u64 sw = 0ull, ax = 0ull, ay = 0ull;            // packed (0.f,0.f)

    const float4* A4 = reinterpret_cast<const float4*>(sA);
    const float4* B4 = reinterpret_cast<const float4*>(sB);
    const float4* D4 = reinterpret_cast<const float4*>(sD);
    const float4* X4 = reinterpret_cast<const float4*>(sX);
    const float4* Y4 = reinterpret_cast<const float4*>(sY);

#pragma unroll 4
    for (int j = 0; j < MPTS / 4; ++j) {
        float4 a  = A4[j];
        float4 bb = B4[j];
        float4 dd = D4[j];
        float4 xx = X4[j];
        float4 yy = Y4[j];
        // targets j*4+0, j*4+1
        {
            u64 r = fma2(pk2(a.x, a.y), vsx, pk2(dd.x, dd.y));
            r = fma2(pk2(bb.x, bb.y), vsy, r);
            r = add2(r, vc0);
            float rl, rh; upk2(r, rl, rh);
            u64 w = pk2(ex2(rl), ex2(rh));          // w = exp(-dist^2), in (0,1]
            sw = add2(sw, w);
            ax = fma2(w, pk2(xx.x, xx.y), ax);
            ay = fma2(w, pk2(yy.x, yy.y), ay);
        }
        // targets j*4+2, j*4+3
        {
            u64 r = fma2(pk2(a.z, a.w), vsx, pk2(dd.z, dd.w));
            r = fma2(pk2(bb.z, bb.w), vsy, r);
            r = add2(r, vc0);
            float rl, rh; upk2(r, rl, rh);
            u64 w = pk2(ex2(rl), ex2(rh));
            sw = add2(sw, w);
            ax = fma2(w, pk2(xx.z, xx.w), ax);
            ay = fma2(w, pk2(yy.z, yy.w), ay);
        }
    }

    float s0, s1, a0, a1, y0, y1;
    upk2(sw, s0, s1); upk2(ax, a0, a1); upk2(ay, y0, y1);
    float inv = __fdividef(1.0f, s0 + s1);
    float tcx = (a0 + a1) * inv;                    // softmax-weighted target_corr
    float tcy = (y0 + y1) * inv;

    // 8 reduction quantities -> warp reduce -> atomic into g_acc[b]
    float vals[8] = { stx, sty, tcx, tcy,
                      stx * tcx, stx * tcy, sty * tcx, sty * tcy };
#pragma unroll
    for (int k = 0; k < 8; k++) {
        float v = vals[k];
        v += __shfl_xor_sync(0xffffffffu, v, 16);
        v += __shfl_xor_sync(0xffffffffu, v, 8);
        v += __shfl_xor_sync(0xffffffffu, v, 4);
        v += __shfl_xor_sync(0xffffffffu, v, 2);
        v += __shfl_xor_sync(0xffffffffu, v, 1);
        if ((tid & 31) == 0) atomicAdd(&g_acc[b][k], v);
    }
}

// ---------------- update: 2x2 Procrustes (V U^T incl. reflection branch), compose T ----------------
__global__ void icp_update(float* __restrict__ out, int last) {
    int b = threadIdx.x;
    if (b >= BATCH) return;
    float* A = g_acc[b];
    float Sx = A[0], Sy = A[1], Px = A[2], Py = A[3];
    float C00 = A[4], C01 = A[5], C10 = A[6], C11 = A[7];
    const float invN = 1.0f / (float)NPTS;

    float csx = Sx * invN, csy = Sy * invN;
    float ctx = Px * invN, cty = Py * invN;
    float h00 = C00 - Sx * Px * invN;
    float h01 = C01 - Sx * Py * invN;
    float h10 = C10 - Sy * Px * invN;
    float h11 = C11 - Sy * Py * invN;

    float E = 0.5f * (h00 + h11);
    float F = 0.5f * (h00 - h11);
    float Z = 0.5f * (h10 - h01);
    float G = 0.5f * (h10 + h01);
    float Q  = sqrtf(E * E + Z * Z);
    float Rr = sqrtf(F * F + G * G);

    float dth, sd, cd, r00, r01, r10, r11;
    if (Q >= Rr) {                         // sy >= 0: proper rotation, polar factor of H^T
        dth = atan2f(-Z, E);
        sincosf(dth, &sd, &cd);
        r00 = cd; r01 = -sd; r10 = sd; r11 = cd;
    } else {                               // sy < 0: V U^T is a reflection
        dth = atan2f(G, F);
        sincosf(dth, &sd, &cd);
        r00 = cd; r01 = sd; r10 = sd; r11 = -cd;
    }
    float tdx = ctx - (r00 * csx + r01 * csy);
    float tdy = cty - (r10 * csx + r11 * csy);

    // T = vec2mat([dth, tdx, tdy]) @ T   (vec2mat always builds a rotation from dth)
    float* T = g_T[b];
    float T00 = T[0], T01 = T[1], T02 = T[2];
    float T10 = T[3], T11 = T[4], T12 = T[5];
    float n00 = cd * T00 - sd * T10;
    float n01 = cd * T01 - sd * T11;
    float n02 = cd * T02 - sd * T12 + tdx;
    float n10 = sd * T00 + cd * T10;
    float n11 = sd * T01 + cd * T11;
    float n12 = sd * T02 + cd * T12 + tdy;
    T[0] = n00; T[1] = n01; T[2] = n02;
    T[3] = n10; T[4] = n11; T[5] = n12;

#pragma unroll
    for (int k = 0; k < 8; k++) A[k] = 0.0f;

    if (last) {
        out[3 * b + 0] = atan2f(n10, n00);
        out[3 * b + 1] = n02;
        out[3 * b + 2] = n12;
    }
}

extern "C" void kernel_launch(void* const* d_in, const int* in_sizes, int n_in,
                              void* d_out, int out_size) {
    const float* source = (const float*)d_in[0];   // [B, N, 2]
    const float* target = (const float*)d_in[1];   // [B, M, 2]
    const float* init_t = (const float*)d_in[2];   // [B, 3]
    float* out = (float*)d_out;                    // [B, 3]

    icp_init<<<1, 32>>>(init_t);
    for (int it = 0; it < ITERS; ++it) {
        dim3 grid(SPLIT, BATCH);
        icp_pair<<<grid, PAIR_THREADS>>>(source, target);
        icp_update<<<1, 32>>>(out, it == ITERS - 1 ? 1 : 0);
    }
}

// round 6
// speedup vs baseline: 1.2004x; 1.2004x over previous
#include <cuda_runtime.h>
#include <cuda_bf16.h>

#define BATCH 32
#define NPTS  2048
#define MPTS  2048
#define ITERS 5
#define PAIR_THREADS 128
#define SPLIT  (NPTS / PAIR_THREADS)   // 16 row-blocks
#define MSPLIT 4
#define MCHUNK (MPTS / MSPLIT)         // 512 targets per CTA
#define LOG2E  1.4426950408889634f
#define INV2L  (0.5f / LOG2E)

// Persistent per-batch state (device globals: no allocation allowed)
__device__ float  g_T[BATCH][6];               // r00 r01 tx  r10 r11 ty
__device__ float  g_acc[BATCH][8];             // Sst.x Sst.y Stc.x Stc.y C00 C01 C10 C11
__device__ float4 g_part[MSPLIT][BATCH * NPTS]; // per-row partial (sw, s_wA, s_wB, 0)

// ---------------- packed f32x2 helpers (sm_100+ PTX) ----------------
typedef unsigned long long u64;

__device__ __forceinline__ u64 pk2(float lo, float hi) {
    u64 r; asm("mov.b64 %0, {%1,%2};" : "=l"(r) : "f"(lo), "f"(hi)); return r;
}
__device__ __forceinline__ void upk2(u64 v, float& lo, float& hi) {
    asm("mov.b64 {%0,%1}, %2;" : "=f"(lo), "=f"(hi) : "l"(v));
}
__device__ __forceinline__ u64 fma2(u64 a, u64 b, u64 c) {
    u64 d; asm("fma.rn.f32x2 %0, %1, %2, %3;" : "=l"(d) : "l"(a), "l"(b), "l"(c)); return d;
}
__device__ __forceinline__ u64 add2(u64 a, u64 b) {
    u64 d; asm("add.rn.f32x2 %0, %1, %2;" : "=l"(d) : "l"(a), "l"(b)); return d;
}
__device__ __forceinline__ float ex2(float x) {
    float r; asm("ex2.approx.f32 %0, %1;" : "=f"(r) : "f"(x)); return r;
}

// ---------------- init: T = vec2mat(init), zero accumulators ----------------
__global__ void icp_init(const float* __restrict__ init) {
    int b = threadIdx.x;
    if (b >= BATCH) return;
    float th = init[3 * b + 0];
    float tx = init[3 * b + 1];
    float ty = init[3 * b + 2];
    float s, c;
    sincosf(th, &s, &c);
    float* T = g_T[b];
    T[0] = c;  T[1] = -s; T[2] = tx;
    T[3] = s;  T[4] = c;  T[5] = ty;
#pragma unroll
    for (int k = 0; k < 8; k++) g_acc[b][k] = 0.0f;
}

// ---------------- pair kernel: one row per thread, one M-chunk per CTA ----------------
// Writes per-row partial sums (additive across chunks: same per-row constant c0
// is used in every chunk, softmax shift-invariance does the rest).
__global__ __launch_bounds__(PAIR_THREADS)
void icp_pair(const float* __restrict__ source, const float* __restrict__ target) {
    __shared__ __align__(16) float sA[MCHUNK];   // 2*log2e*tx
    __shared__ __align__(16) float sB[MCHUNK];   // 2*log2e*ty
    __shared__ __align__(16) float sD[MCHUNK];   // -log2e*|t|^2

    const int b   = blockIdx.z;
    const int ms  = blockIdx.y;
    const int tid = threadIdx.x;

    const float2* t2 = reinterpret_cast<const float2*>(target) + b * MPTS + ms * MCHUNK;
#pragma unroll
    for (int j = tid; j < MCHUNK; j += PAIR_THREADS) {
        float2 t = t2[j];
        sA[j] = 2.0f * LOG2E * t.x;
        sB[j] = 2.0f * LOG2E * t.y;
        sD[j] = -LOG2E * (t.x * t.x + t.y * t.y);
    }

    // transform this thread's source row: st = R*s + t
    const float* T = g_T[b];
    const int row = blockIdx.x * PAIR_THREADS + tid;
    const float2 s2 = reinterpret_cast<const float2*>(source)[b * NPTS + row];
    float stx = T[0] * s2.x + T[1] * s2.y + T[2];
    float sty = T[3] * s2.x + T[4] * s2.y + T[5];
    float c0  = -LOG2E * (stx * stx + sty * sty);  // arg == -log2e*dist^2 exactly

    __syncthreads();

    u64 vsx = pk2(stx, stx);
    u64 vsy = pk2(sty, sty);
    u64 vc0 = pk2(c0, c0);
    u64 sw = 0ull, ax = 0ull, ay = 0ull;

    const float4* A4 = reinterpret_cast<const float4*>(sA);
    const float4* B4 = reinterpret_cast<const float4*>(sB);
    const float4* D4 = reinterpret_cast<const float4*>(sD);

#pragma unroll 4
    for (int j = 0; j < MCHUNK / 4; ++j) {
        float4 a  = A4[j];
        float4 bb = B4[j];
        float4 dd = D4[j];
        // targets 4j, 4j+1
        {
            u64 va = pk2(a.x, a.y);
            u64 vb = pk2(bb.x, bb.y);
            u64 r = fma2(va, vsx, pk2(dd.x, dd.y));
            r = fma2(vb, vsy, r);
            r = add2(r, vc0);
            float rl, rh; upk2(r, rl, rh);
            u64 w = pk2(ex2(rl), ex2(rh));   // w = exp(-dist^2) in (0,1]
            sw = add2(sw, w);
            ax = fma2(w, va, ax);            // accumulates w * 2L*tx
            ay = fma2(w, vb, ay);            // accumulates w * 2L*ty
        }
        // targets 4j+2, 4j+3
        {
            u64 va = pk2(a.z, a.w);
            u64 vb = pk2(bb.z, bb.w);
            u64 r = fma2(va, vsx, pk2(dd.z, dd.w));
            r = fma2(vb, vsy, r);
            r = add2(r, vc0);
            float rl, rh; upk2(r, rl, rh);
            u64 w = pk2(ex2(rl), ex2(rh));
            sw = add2(sw, w);
            ax = fma2(w, va, ax);
            ay = fma2(w, vb, ay);
        }
    }

    float s0, s1, a0, a1, y0, y1;
    upk2(sw, s0, s1); upk2(ax, a0, a1); upk2(ay, y0, y1);
    g_part[ms][b * NPTS + row] = make_float4(s0 + s1, a0 + a1, y0 + y1, 0.0f);
}

// ---------------- reduce: combine M-chunk partials, accumulate the 8 moments ----------------
__global__ __launch_bounds__(256)
void icp_reduce(const float* __restrict__ source) {
    __shared__ float red[8][8];   // [warp][component]

    const int b   = blockIdx.y;
    const int tid = threadIdx.x;
    const int row = blockIdx.x * 256 + tid;
    const int idx = b * NPTS + row;

    float sw = 0.0f, axs = 0.0f, ays = 0.0f;
#pragma unroll
    for (int ms = 0; ms < MSPLIT; ms++) {
        float4 p = g_part[ms][idx];
        sw += p.x; axs += p.y; ays += p.z;
    }
    float inv = __fdividef(INV2L, sw);
    float tcx = axs * inv;    // softmax-weighted target_corr
    float tcy = ays * inv;

    const float* T = g_T[b];
    const float2 s2 = reinterpret_cast<const float2*>(source)[idx];
    float stx = T[0] * s2.x + T[1] * s2.y + T[2];
    float sty = T[3] * s2.x + T[4] * s2.y + T[5];

    float vals[8] = { stx, sty, tcx, tcy,
                      stx * tcx, stx * tcy, sty * tcx, sty * tcy };
#pragma unroll
    for (int k = 0; k < 8; k++) {
        float v = vals[k];
        v += __shfl_xor_sync(0xffffffffu, v, 16);
        v += __shfl_xor_sync(0xffffffffu, v, 8);
        v += __shfl_xor_sync(0xffffffffu, v, 4);
        v += __shfl_xor_sync(0xffffffffu, v, 2);
        v += __shfl_xor_sync(0xffffffffu, v, 1);
        vals[k] = v;
    }
    if ((tid & 31) == 0) {
        int w = tid >> 5;
#pragma unroll
        for (int k = 0; k < 8; k++) red[w][k] = vals[k];
    }
    __syncthreads();
    if (tid < 8) {
        float v = red[0][tid];
#pragma unroll
        for (int w = 1; w < 8; w++) v += red[w][tid];
        atomicAdd(&g_acc[b][tid], v);
    }
}

// ---------------- update: 2x2 Procrustes (V U^T incl. reflection branch), compose T ----------------
__global__ void icp_update(float* __restrict__ out, int last) {
    int b = threadIdx.x;
    if (b >= BATCH) return;
    float* A = g_acc[b];
    float Sx = A[0], Sy = A[1], Px = A[2], Py = A[3];
    float C00 = A[4], C01 = A[5], C10 = A[6], C11 = A[7];
    const float invN = 1.0f / (float)NPTS;

    float csx = Sx * invN, csy = Sy * invN;
    float ctx = Px * invN, cty = Py * invN;
    float h00 = C00 - Sx * Px * invN;
    float h01 = C01 - Sx * Py * invN;
    float h10 = C10 - Sy * Px * invN;
    float h11 = C11 - Sy * Py * invN;

    float E = 0.5f * (h00 + h11);
    float F = 0.5f * (h00 - h11);
    float Z = 0.5f * (h10 - h01);
    float G = 0.5f * (h10 + h01);
    float Q  = sqrtf(E * E + Z * Z);
    float Rr = sqrtf(F * F + G * G);

    float dth, sd, cd, r00, r01, r10, r11;
    if (Q >= Rr) {                         // proper rotation: polar factor of H^T
        dth = atan2f(-Z, E);
        sincosf(dth, &sd, &cd);
        r00 = cd; r01 = -sd; r10 = sd; r11 = cd;
    } else {                               // V U^T is a reflection
        dth = atan2f(G, F);
        sincosf(dth, &sd, &cd);
        r00 = cd; r01 = sd; r10 = sd; r11 = -cd;
    }
    float tdx = ctx - (r00 * csx + r01 * csy);
    float tdy = cty - (r10 * csx + r11 * csy);

    float* T = g_T[b];
    float T00 = T[0], T01 = T[1], T02 = T[2];
    float T10 = T[3], T11 = T[4], T12 = T[5];
    float n00 = cd * T00 - sd * T10;
    float n01 = cd * T01 - sd * T11;
    float n02 = cd * T02 - sd * T12 + tdx;
    float n10 = sd * T00 + cd * T10;
    float n11 = sd * T01 + cd * T11;
    float n12 = sd * T02 + cd * T12 + tdy;
    T[0] = n00; T[1] = n01; T[2] = n02;
    T[3] = n10; T[4] = n11; T[5] = n12;

#pragma unroll
    for (int k = 0; k < 8; k++) A[k] = 0.0f;

    if (last) {
        out[3 * b + 0] = atan2f(n10, n00);
        out[3 * b + 1] = n02;
        out[3 * b + 2] = n12;
    }
}

extern "C" void kernel_launch(void* const* d_in, const int* in_sizes, int n_in,
                              void* d_out, int out_size) {
    const float* source = (const float*)d_in[0];   // [B, N, 2]
    const float* target = (const float*)d_in[1];   // [B, M, 2]
    const float* init_t = (const float*)d_in[2];   // [B, 3]
    float* out = (float*)d_out;                    // [B, 3]

    icp_init<<<1, 32>>>(init_t);
    for (int it = 0; it < ITERS; ++it) {
        dim3 pgrid(SPLIT, MSPLIT, BATCH);          // 16 x 4 x 32 = 2048 CTAs
        icp_pair<<<pgrid, PAIR_THREADS>>>(source, target);
        dim3 rgrid(NPTS / 256, BATCH);
        icp_reduce<<<rgrid, 256>>>(source);
        icp_update<<<1, 32>>>(out, it == ITERS - 1 ? 1 : 0);
    }
}